// round 14
// baseline (speedup 1.0000x reference)
#include <cuda_runtime.h>
#include <cuda_fp16.h>

// Problem constants
#define HH    64
#define TT    32
#define BB    4096
#define AA    6
#define MROWS 32        // batch rows per lstm CTA

// lstm smem layout (bytes). Rows padded to 144B (72 halves) for conflict-free ldmatrix.
#define OFF_WS  0                    // Ws [256][72] half : weights fp16 (i/f/o pre-scaled 0.5)
#define OFF_HS  36864                // hs double buffer: 2 x [32][72] half
#define HS_BUF  4608                 // bytes per h buffer
#define OFF_WBS 46080                // float2[256] permuted {wih, b} (final step only)
#define OFF_XS  48128                // float [32][33]
#define LSTM_PART_BYTES (OFF_XS + 32 * 33 * 4)   // 52352

// fused head overlay (reuses smem after lstm phase; union with lstm layout)
#define H_AH 0                       // A fp16 [32][264]
#define H_BH 16896                   // B fp16 [64][264]
#define H_QB 50688                   // qb fp32 [32][66]
#define H_IB 59136                   // ib fp32 [32][8]
#define H_FLAG 60160                 // int winner flag
#define SMEM_BYTES 60416             // max(lstm 52352, head 60164) padded; 2 CTAs/SM

// scratch: final hidden states fp16, [B][192] (3 LSTM outputs per branch)
__device__ __half g_hq[BB * 192];
__device__ __half g_hi[BB * 192];
// tile completion counters [128 tiles][2 branches]; each launch: 0 -> 3 -> reset 0
__device__ int g_cnt[256];

__device__ __forceinline__ float tanh_ap(float x) {
    float y;
    asm("tanh.approx.f32 %0, %1;" : "=f"(y) : "f"(x));
    return y;
}
__device__ __forceinline__ __half2 tanh2_ap(__half2 x) {
    __half2 y;
    asm("tanh.approx.f16x2 %0, %1;" : "=r"(*(unsigned*)&y) : "r"(*(unsigned*)&x));
    return y;
}

__device__ __forceinline__ unsigned smem_u32(const void* p) {
    unsigned a;
    asm("{ .reg .u64 t; cvta.to.shared.u64 t, %1; cvt.u32.u64 %0, t; }" : "=r"(a) : "l"(p));
    return a;
}
__device__ __forceinline__ void ldsm_x4(unsigned addr, unsigned& r0, unsigned& r1,
                                        unsigned& r2, unsigned& r3) {
    asm volatile("ldmatrix.sync.aligned.m8n8.x4.shared.b16 {%0,%1,%2,%3}, [%4];"
                 : "=r"(r0), "=r"(r1), "=r"(r2), "=r"(r3) : "r"(addr));
}
// fp32-acc HMMA
__device__ __forceinline__ void mma16816(float& d0, float& d1, float& d2, float& d3,
                                         unsigned a0, unsigned a1, unsigned a2, unsigned a3,
                                         unsigned b0, unsigned b1) {
    asm volatile(
        "mma.sync.aligned.m16n8k16.row.col.f32.f16.f16.f32 "
        "{%0,%1,%2,%3}, {%4,%5,%6,%7}, {%8,%9}, {%0,%1,%2,%3};"
        : "+f"(d0), "+f"(d1), "+f"(d2), "+f"(d3)
        : "r"(a0), "r"(a1), "r"(a2), "r"(a3), "r"(b0), "r"(b1));
}
// fp16-acc HMMA, accumulate into d
__device__ __forceinline__ void mma_h_acc(unsigned& d0, unsigned& d1,
                                          unsigned a0, unsigned a1, unsigned a2, unsigned a3,
                                          unsigned b0, unsigned b1) {
    asm volatile(
        "mma.sync.aligned.m16n8k16.row.col.f16.f16.f16.f16 "
        "{%0,%1}, {%2,%3,%4,%5}, {%6,%7}, {%0,%1};"
        : "+r"(d0), "+r"(d1)
        : "r"(a0), "r"(a1), "r"(a2), "r"(a3), "r"(b0), "r"(b1));
}
// fp16-acc HMMA, C = 0
__device__ __forceinline__ void mma_h_zero(unsigned& d0, unsigned& d1,
                                           unsigned a0, unsigned a1, unsigned a2, unsigned a3,
                                           unsigned b0, unsigned b1) {
    asm volatile(
        "mma.sync.aligned.m16n8k16.row.col.f16.f16.f16.f16 "
        "{%0,%1}, {%2,%3,%4,%5}, {%6,%7}, {%8,%8};"
        : "=r"(d0), "=r"(d1)
        : "r"(a0), "r"(a1), "r"(a2), "r"(a3), "r"(b0), "r"(b1), "r"(0u));
}
__device__ __forceinline__ void bar_group(int id) {
    asm volatile("bar.sync %0, 128;" :: "r"(id) : "memory");
}

// One CTA: 32 batch rows x one LSTM run (grid 128 x 6). After the final step,
// CTAs arrive on a per-(tile, branch) atomic counter; the 3rd arriver runs the
// fused head for its 32-row tile in-place (smem reused), overlapping the head
// with the lstm tail instead of paying a separate latency-bound kernel.
__global__ __launch_bounds__(256, 2) void lstm_fused_kernel(
    const float* __restrict__ x0, const float* __restrict__ x1, const float* __restrict__ x2,
    const float* __restrict__ q00_wih, const float* __restrict__ q00_whh, const float* __restrict__ q00_b,
    const float* __restrict__ q01_wih, const float* __restrict__ q01_whh, const float* __restrict__ q01_b,
    const float* __restrict__ i00_wih, const float* __restrict__ i00_whh, const float* __restrict__ i00_b,
    const float* __restrict__ i01_wih, const float* __restrict__ i01_whh, const float* __restrict__ i01_b,
    const float* __restrict__ i02_wih, const float* __restrict__ i02_whh, const float* __restrict__ i02_b,
    const float* __restrict__ s2,
    const float* __restrict__ q03_w, const float* __restrict__ q03_b,
    const float* __restrict__ q1_w,  const float* __restrict__ q1_b,
    const float* __restrict__ q2_w,  const float* __restrict__ q2_b,
    const float* __restrict__ i03_w, const float* __restrict__ i03_b,
    const float* __restrict__ i1_w,  const float* __restrict__ i1_b,
    const float* __restrict__ i2_w,  const float* __restrict__ i2_b,
    float* __restrict__ out)
{
    extern __shared__ char smem[];
    const unsigned sb = smem_u32(smem);

    const float* x; const float* wih; const float* whh; const float* bias;
    __half* hout; int coloff;
    switch (blockIdx.y) {
        case 0:  x = x0; wih = q00_wih; whh = q00_whh; bias = q00_b; hout = g_hq; coloff = 0;   break;
        case 1:  x = x1; wih = q01_wih; whh = q01_whh; bias = q01_b; hout = g_hq; coloff = 64;  break;
        case 2:  x = x2; wih = q01_wih; whh = q01_whh; bias = q01_b; hout = g_hq; coloff = 128; break;
        case 3:  x = x0; wih = i00_wih; whh = i00_whh; bias = i00_b; hout = g_hi; coloff = 0;   break;
        case 4:  x = x1; wih = i01_wih; whh = i01_whh; bias = i01_b; hout = g_hi; coloff = 64;  break;
        default: x = x2; wih = i02_wih; whh = i02_whh; bias = i02_b; hout = g_hi; coloff = 128; break;
    }

    const int tid  = threadIdx.x;
    const int wid  = tid >> 5;
    const int lane = tid & 31;
    const int rg   = wid & 1;        // 16-row group
    const int gq   = wid >> 1;       // 64-gate quarter (0..3)
    const int g    = lane >> 2;
    const int tl   = lane & 3;
    const int r0g  = blockIdx.x * MROWS;

    // ---- stage whh fp16, permuted, 0.5-scaled for i/f/o (tg != 2) ----
    __half* ws = (__half*)(smem + OFF_WS);
    for (int idx = tid; idx < 256 * 64; idx += 256) {
        int go = idx >> 6, k = idx & 63;
        int tg = go >> 6, u = go & 63;
        int p  = (u & 3) * 2 + (tg & 1) + 8 * (tg >> 1) + 16 * (u >> 2);
        float sc = (tg == 2) ? 1.0f : 0.5f;
        ws[p * 72 + k] = __float2half(whh[idx] * sc);
    }
    // permuted {wih, b} table (final fp32 step only), same 0.5 scale for i/f/o
    {
        int go = tid;
        int tg = go >> 6, u = go & 63;
        int p  = (u & 3) * 2 + (tg & 1) + 8 * (tg >> 1) + 16 * (u >> 2);
        float sc = (tg == 2) ? 1.0f : 0.5f;
        ((float2*)(smem + OFF_WBS))[p] = make_float2(wih[go] * sc, bias[go] * sc);
    }
    // x tile [32][33]
    float* xs = (float*)(smem + OFF_XS);
    for (int idx = tid; idx < MROWS * TT; idx += 256) {
        int r = idx >> 5, tt = idx & 31;
        xs[r * 33 + tt] = x[(size_t)(r0g + r) * TT + tt];
    }
    __syncthreads();

    // per-lane ldmatrix addresses
    const int rowA  = rg * 16 + (lane & 7) + 8 * ((lane >> 3) & 1);
    const unsigned aoff = (unsigned)(rowA * 144 + (lane >> 4) * 16);
    const int rowBb = gq * 64 + (lane & 7) + 8 * (lane >> 4);
    const unsigned boff = (unsigned)(rowBb * 144 + ((lane >> 3) & 1) * 16);

    const int r0 = rg * 16 + g;       // this thread's rows
    const int r1 = r0 + 8;

    // hoist B fragments for kc = 0,1 into registers (static weights)
    unsigned bw[8][4];
    #pragma unroll
    for (int kc = 0; kc < 2; ++kc)
        #pragma unroll
        for (int np = 0; np < 4; ++np)
            ldsm_x4(sb + OFF_WS + boff + (unsigned)(np * 16 * 144 + kc * 32),
                    bw[kc * 4 + np][0], bw[kc * 4 + np][1],
                    bw[kc * 4 + np][2], bw[kc * 4 + np][3]);

    // hoisted half2 fold constants: per q, unit u = 16gq + 4q + tl
    __half2 w_if2[4], b_if2[4], w_go2[4], b_go2[4];
    #pragma unroll
    for (int q = 0; q < 4; ++q) {
        int u = 16 * gq + 4 * q + tl;
        w_if2[q] = __floats2half2_rn(0.5f * wih[u], 0.5f * wih[64 + u]);
        b_if2[q] = __floats2half2_rn(0.5f * bias[u], 0.5f * bias[64 + u]);
        w_go2[q] = __floats2half2_rn(wih[128 + u], 0.5f * wih[192 + u]);
        b_go2[q] = __floats2half2_rn(bias[128 + u], 0.5f * bias[192 + u]);
    }

    __half2 c2[4];
    #pragma unroll
    for (int i = 0; i < 4; ++i) c2[i] = __floats2half2_rn(0.f, 0.f);

    const __half2 h05   = __floats2half2_rn(0.5f, 0.5f);
    const __half2 m1_05 = __floats2half2_rn(1.0f, 0.5f);
    const __half2 a0_05 = __floats2half2_rn(0.0f, 0.5f);
    const int barid = 1 + rg;

    unsigned aif[4][2], ago[4][2];
    #pragma unroll
    for (int np = 0; np < 4; ++np) {
        aif[np][0] = aif[np][1] = 0u;
        ago[np][0] = ago[np][1] = 0u;
    }

    #pragma unroll 1
    for (int t = 0; t < TT - 1; ++t) {
        if (t > 0) {
            const unsigned rbase = sb + OFF_HS + ((unsigned)((t + 1) & 1)) * HS_BUF;
            #pragma unroll
            for (int kc = 0; kc < 4; ++kc) {
                unsigned ah0, ah1, ah2, ah3;
                ldsm_x4(rbase + aoff + kc * 32, ah0, ah1, ah2, ah3);
                #pragma unroll
                for (int np = 0; np < 4; ++np) {
                    unsigned b0, b1, b2, b3;
                    if (kc < 2) {
                        b0 = bw[kc * 4 + np][0]; b1 = bw[kc * 4 + np][1];
                        b2 = bw[kc * 4 + np][2]; b3 = bw[kc * 4 + np][3];
                    } else {
                        ldsm_x4(sb + OFF_WS + boff + (unsigned)(np * 16 * 144 + kc * 32),
                                b0, b1, b2, b3);
                    }
                    if (kc == 0) {
                        mma_h_zero(aif[np][0], aif[np][1], ah0, ah1, ah2, ah3, b0, b1);
                        mma_h_zero(ago[np][0], ago[np][1], ah0, ah1, ah2, ah3, b2, b3);
                    } else {
                        mma_h_acc(aif[np][0], aif[np][1], ah0, ah1, ah2, ah3, b0, b1);
                        mma_h_acc(ago[np][0], ago[np][1], ah0, ah1, ah2, ah3, b2, b3);
                    }
                }
            }
        }

        // pure-half2 epilogue
        __half* hw = (__half*)(smem + OFF_HS + (t & 1) * HS_BUF);
        __half2 xh0 = __half2half2(__float2half(xs[r0 * 33 + t]));
        __half2 xh1 = __half2half2(__float2half(xs[r1 * 33 + t]));
        #pragma unroll
        for (int q = 0; q < 4; ++q) {
            int u = 16 * gq + 4 * q + tl;
            __half2 if0 = __hadd2(*(__half2*)&aif[q][0], __hfma2(w_if2[q], xh0, b_if2[q]));
            __half2 if1 = __hadd2(*(__half2*)&aif[q][1], __hfma2(w_if2[q], xh1, b_if2[q]));
            __half2 go0 = __hadd2(*(__half2*)&ago[q][0], __hfma2(w_go2[q], xh0, b_go2[q]));
            __half2 go1 = __hadd2(*(__half2*)&ago[q][1], __hfma2(w_go2[q], xh1, b_go2[q]));

            __half2 sif0 = __hfma2(tanh2_ap(if0), h05, h05);
            __half2 sif1 = __hfma2(tanh2_ap(if1), h05, h05);
            __half2 gso0 = __hfma2(tanh2_ap(go0), m1_05, a0_05);
            __half2 gso1 = __hfma2(tanh2_ap(go1), m1_05, a0_05);

            __half2 si2 = __lows2half2(sif0, sif1);
            __half2 sf2 = __highs2half2(sif0, sif1);
            __half2 tg2 = __lows2half2(gso0, gso1);
            __half2 so2 = __highs2half2(gso0, gso1);
            c2[q] = __hfma2(sf2, c2[q], __hmul2(si2, tg2));
            __half2 h2v = __hmul2(so2, tanh2_ap(c2[q]));
            hw[r0 * 72 + u] = __low2half(h2v);
            hw[r1 * 72 + u] = __high2half(h2v);
        }
        bar_group(barid);
    }

    // ---- final step (t = TT-1): fp32-acc MMA + fp32 epilogue, fp16 store ----
    {
        const int t = TT - 1;
        float acc[32];
        #pragma unroll
        for (int i = 0; i < 32; ++i) acc[i] = 0.f;
        const unsigned rbase = sb + OFF_HS + ((unsigned)((t + 1) & 1)) * HS_BUF;
        #pragma unroll
        for (int kc = 0; kc < 4; ++kc) {
            unsigned ah0, ah1, ah2, ah3;
            ldsm_x4(rbase + aoff + kc * 32, ah0, ah1, ah2, ah3);
            #pragma unroll
            for (int np = 0; np < 4; ++np) {
                unsigned b0, b1, b2, b3;
                if (kc < 2) {
                    b0 = bw[kc * 4 + np][0]; b1 = bw[kc * 4 + np][1];
                    b2 = bw[kc * 4 + np][2]; b3 = bw[kc * 4 + np][3];
                } else {
                    ldsm_x4(sb + OFF_WS + boff + (unsigned)(np * 16 * 144 + kc * 32),
                            b0, b1, b2, b3);
                }
                float* e = acc + np * 8;
                mma16816(e[0], e[1], e[2], e[3], ah0, ah1, ah2, ah3, b0, b1);
                mma16816(e[4], e[5], e[6], e[7], ah0, ah1, ah2, ah3, b2, b3);
            }
        }
        const float4* wbs4 = (const float4*)(smem + OFF_WBS);
        float xv0 = xs[r0 * 33 + t];
        float xv1 = xs[r1 * 33 + t];
        #pragma unroll
        for (int q = 0; q < 4; ++q) {
            int pq = 16 * (gq * 4 + q) + 2 * tl;
            float4 wif = wbs4[pq >> 1];
            float4 wgo = wbs4[(pq >> 1) + 4];
            int u = 16 * gq + 4 * q + tl;
            float2 cf = __half22float2(c2[q]);
            #pragma unroll
            for (int rowj = 0; rowj < 2; ++rowj) {
                float xv = rowj ? xv1 : xv0;
                float iv = acc[8 * q + rowj * 2 + 0] + fmaf(wif.x, xv, wif.y);
                float fv = acc[8 * q + rowj * 2 + 1] + fmaf(wif.z, xv, wif.w);
                float gv = acc[8 * q + 4 + rowj * 2 + 0] + fmaf(wgo.x, xv, wgo.y);
                float ov = acc[8 * q + 4 + rowj * 2 + 1] + fmaf(wgo.z, xv, wgo.w);
                float si = fmaf(0.5f, tanh_ap(iv), 0.5f);
                float sf = fmaf(0.5f, tanh_ap(fv), 0.5f);
                float so = fmaf(0.5f, tanh_ap(ov), 0.5f);
                float cold = rowj ? cf.y : cf.x;
                float cc = sf * cold + si * tanh_ap(gv);
                float h = so * tanh_ap(cc);
                int row = rowj ? r1 : r0;
                hout[(size_t)(r0g + row) * 192 + coloff + u] = __float2half(h);
            }
        }
    }

    // ---- tile-completion handshake: 3rd arriver runs the fused head ----
    const int br = (blockIdx.y >= 3) ? 1 : 0;
    int* flag = (int*)(smem + H_FLAG);
    __threadfence();          // release hout stores
    __syncthreads();          // all lstm smem reads done; all threads fenced
    if (tid == 0) {
        int old = atomicAdd(&g_cnt[blockIdx.x * 2 + br], 1);
        *flag = (old == 2) ? 1 : 0;
        if (old == 2) g_cnt[blockIdx.x * 2 + br] = 0;   // reset for next launch
    }
    __syncthreads();
    if (*flag == 0) return;
    __threadfence();          // acquire: peer CTAs' hout stores visible

    // ================= fused head for (tile = blockIdx.x, branch = br) =======
    __half* Ah = (__half*)(smem + H_AH);       // [32][264]
    __half* Bh = (__half*)(smem + H_BH);       // [64][264]
    float* qb  = (float*)(smem + H_QB);        // [32][66]
    float* ib  = (float*)(smem + H_IB);        // [32][8]

    const int row0 = blockIdx.x * 32;
    const __half* gh = br ? g_hi  : g_hq;
    const float* w03 = br ? i03_w : q03_w;
    const float* b03 = br ? i03_b : q03_b;
    const float* w1  = br ? i1_w  : q1_w;
    const float* b1  = br ? i1_b  : q1_b;
    const float* w2  = br ? i2_w  : q2_w;
    const float* b2  = br ? i2_b  : q2_b;

    // stage A cols [0:192): raw uint4 copy of fp16 hidden states
    for (int idx = tid; idx < 32 * 24; idx += 256) {
        int r = idx / 24, c8 = idx - r * 24;
        uint4 v = *(const uint4*)&gh[(size_t)(row0 + r) * 192 + c8 * 8];
        *(uint4*)&Ah[r * 264 + c8 * 8] = v;
    }
    // stage A cols [192:256): relu(s2 @ w03 + b03)
    for (int idx = tid; idx < 32 * 64; idx += 256) {
        int r = idx >> 6, u = idx & 63;
        const float* s = &s2[(row0 + r) * 3];
        float a = b03[u] + s[0] * w03[u * 3] + s[1] * w03[u * 3 + 1] + s[2] * w03[u * 3 + 2];
        Ah[r * 264 + 192 + u] = __float2half(fmaxf(a, 0.f));
    }
    // stage B = w1 [64 u][256 k]
    for (int idx = tid; idx < 64 * 64; idx += 256) {
        int u = idx >> 6, k4 = idx & 63;
        float4 v = *(const float4*)&w1[u * 256 + k4 * 4];
        __half2* d = (__half2*)&Bh[u * 264 + k4 * 4];
        d[0] = __floats2half2_rn(v.x, v.y);
        d[1] = __floats2half2_rn(v.z, v.w);
    }
    __syncthreads();

    // GEMM1: warp (mt, nq): rows mt*16..+15, cols nq*16..+15
    {
        const int mt = wid & 1;
        const int nq = wid >> 1;
        const unsigned abase = sb + H_AH +
            (unsigned)((mt * 16 + (lane & 7) + 8 * ((lane >> 3) & 1)) * 528 + (lane >> 4) * 16);
        const unsigned bbase = sb + H_BH +
            (unsigned)((nq * 16 + (lane & 7) + 8 * (lane >> 4)) * 528 + ((lane >> 3) & 1) * 16);

        float acc[8];
        #pragma unroll
        for (int i = 0; i < 8; ++i) acc[i] = 0.f;

        #pragma unroll
        for (int kc = 0; kc < 16; ++kc) {
            unsigned a0, a1, a2, a3, b0, b1, b2, b3;
            ldsm_x4(abase + kc * 32, a0, a1, a2, a3);
            ldsm_x4(bbase + kc * 32, b0, b1, b2, b3);
            mma16816(acc[0], acc[1], acc[2], acc[3], a0, a1, a2, a3, b0, b1);
            mma16816(acc[4], acc[5], acc[6], acc[7], a0, a1, a2, a3, b2, b3);
        }

        const int r0h = mt * 16 + g;
        const int r1h = r0h + 8;
        #pragma unroll
        for (int nt = 0; nt < 2; ++nt) {
            int col = nq * 16 + nt * 8 + tl * 2;
            float bb0 = b1[col], bb1 = b1[col + 1];
            qb[r0h * 66 + col]     = fmaxf(acc[nt * 4 + 0] + bb0, 0.f);
            qb[r0h * 66 + col + 1] = fmaxf(acc[nt * 4 + 1] + bb1, 0.f);
            qb[r1h * 66 + col]     = fmaxf(acc[nt * 4 + 2] + bb0, 0.f);
            qb[r1h * 66 + col + 1] = fmaxf(acc[nt * 4 + 3] + bb1, 0.f);
        }
    }
    __syncthreads();

    // GEMV2: 32 rows x 6 outputs
    if (tid < 32 * AA) {
        int r = tid / AA;
        int a = tid - r * AA;
        float acc2 = b2[a];
        #pragma unroll 8
        for (int k = 0; k < 64; ++k)
            acc2 = fmaf(w2[a * 64 + k], qb[r * 66 + k], acc2);
        if (br == 0) out[(row0 + r) * AA + a] = acc2;        // q (no relu)
        else         ib[r * 8 + a] = fmaxf(acc2, 0.f);       // i vec
    }
    if (br == 1) {
        __syncthreads();
        if (tid < 32) {
            int r = tid;
            float m = ib[r * 8];
            #pragma unroll
            for (int j = 1; j < AA; ++j) m = fmaxf(m, ib[r * 8 + j]);
            float s = 0.f;
            #pragma unroll
            for (int j = 0; j < AA; ++j) s += __expf(ib[r * 8 + j] - m);
            float lse = m + __logf(s);
            #pragma unroll
            for (int j = 0; j < AA; ++j) {
                float iv = ib[r * 8 + j];
                out[BB * AA + (row0 + r) * AA + j]     = iv - lse;
                out[2 * BB * AA + (row0 + r) * AA + j] = iv;
            }
        }
    }
}

extern "C" void kernel_launch(void* const* d_in, const int* in_sizes, int n_in,
                              void* d_out, int out_size)
{
    const float* x0 = (const float*)d_in[0];
    const float* x1 = (const float*)d_in[1];
    const float* x2 = (const float*)d_in[2];
    const float* s2 = (const float*)d_in[3];
    const float* q00_wih = (const float*)d_in[4];
    const float* q00_whh = (const float*)d_in[5];
    const float* q00_b   = (const float*)d_in[6];
    const float* q01_wih = (const float*)d_in[7];
    const float* q01_whh = (const float*)d_in[8];
    const float* q01_b   = (const float*)d_in[9];
    const float* i00_wih = (const float*)d_in[10];
    const float* i00_whh = (const float*)d_in[11];
    const float* i00_b   = (const float*)d_in[12];
    const float* i01_wih = (const float*)d_in[13];
    const float* i01_whh = (const float*)d_in[14];
    const float* i01_b   = (const float*)d_in[15];
    const float* i02_wih = (const float*)d_in[16];
    const float* i02_whh = (const float*)d_in[17];
    const float* i02_b   = (const float*)d_in[18];
    const float* q03_w = (const float*)d_in[19];
    const float* q03_b = (const float*)d_in[20];
    const float* q1_w  = (const float*)d_in[21];
    const float* q1_b  = (const float*)d_in[22];
    const float* q2_w  = (const float*)d_in[23];
    const float* q2_b  = (const float*)d_in[24];
    const float* i03_w = (const float*)d_in[25];
    const float* i03_b = (const float*)d_in[26];
    const float* i1_w  = (const float*)d_in[27];
    const float* i1_b  = (const float*)d_in[28];
    const float* i2_w  = (const float*)d_in[29];
    const float* i2_b  = (const float*)d_in[30];
    float* out = (float*)d_out;

    cudaFuncSetAttribute(lstm_fused_kernel, cudaFuncAttributeMaxDynamicSharedMemorySize, SMEM_BYTES);

    dim3 grid(BB / MROWS, 6);   // 128 tiles x 6 LSTM runs = 768 CTAs, 2/SM
    lstm_fused_kernel<<<grid, 256, SMEM_BYTES>>>(
        x0, x1, x2,
        q00_wih, q00_whh, q00_b,
        q01_wih, q01_whh, q01_b,
        i00_wih, i00_whh, i00_b,
        i01_wih, i01_whh, i01_b,
        i02_wih, i02_whh, i02_b,
        s2,
        q03_w, q03_b, q1_w, q1_b, q2_w, q2_b,
        i03_w, i03_b, i1_w, i1_b, i2_w, i2_b,
        out);
}

// round 16
// speedup vs baseline: 1.0377x; 1.0377x over previous
#include <cuda_runtime.h>
#include <cuda_fp16.h>

// Problem constants
#define HH    64
#define TT    32
#define BB    4096
#define AA    6
#define MROWS 32        // batch rows per lstm CTA

// lstm smem layout (bytes). Rows padded to 144B (72 halves) for conflict-free ldmatrix.
#define OFF_WS  0                    // Ws [256][72] half : weights fp16 (i/f/o pre-scaled 0.5)
#define OFF_HS  36864                // hs double buffer: 2 x [32][72] half
#define HS_BUF  4608                 // bytes per h buffer
#define OFF_WBS 46080                // float2[256] permuted {wih, b} (final step only)
#define OFF_XS  48128                // float [32][33]
#define LSTM_SMEM_BYTES (OFF_XS + 32 * 33 * 4)   // 52352 -> 3 CTAs/SM

// head kernel (HMMA, 32 rows/CTA): grid (128, 2) = 256 CTAs.
#define H_AH 0                       // A fp16 [32][264]
#define H_BH 16896                   // B fp16 [64][264]
#define H_QB 50688                   // qb fp32 [32][66]
#define H_IB 59136                   // ib fp32 [32][8]
#define HEAD_SMEM_BYTES (H_IB + 1536)

// scratch: final hidden states fp16, [B][192] (3 LSTM outputs per branch)
__device__ __half g_hq[BB * 192];
__device__ __half g_hi[BB * 192];

__device__ __forceinline__ float tanh_ap(float x) {
    float y;
    asm("tanh.approx.f32 %0, %1;" : "=f"(y) : "f"(x));
    return y;
}
__device__ __forceinline__ __half2 tanh2_ap(__half2 x) {
    __half2 y;
    asm("tanh.approx.f16x2 %0, %1;" : "=r"(*(unsigned*)&y) : "r"(*(unsigned*)&x));
    return y;
}

__device__ __forceinline__ unsigned smem_u32(const void* p) {
    unsigned a;
    asm("{ .reg .u64 t; cvta.to.shared.u64 t, %1; cvt.u32.u64 %0, t; }" : "=r"(a) : "l"(p));
    return a;
}
__device__ __forceinline__ void ldsm_x4(unsigned addr, unsigned& r0, unsigned& r1,
                                        unsigned& r2, unsigned& r3) {
    asm volatile("ldmatrix.sync.aligned.m8n8.x4.shared.b16 {%0,%1,%2,%3}, [%4];"
                 : "=r"(r0), "=r"(r1), "=r"(r2), "=r"(r3) : "r"(addr));
}
// fp32-acc HMMA
__device__ __forceinline__ void mma16816(float& d0, float& d1, float& d2, float& d3,
                                         unsigned a0, unsigned a1, unsigned a2, unsigned a3,
                                         unsigned b0, unsigned b1) {
    asm volatile(
        "mma.sync.aligned.m16n8k16.row.col.f32.f16.f16.f32 "
        "{%0,%1,%2,%3}, {%4,%5,%6,%7}, {%8,%9}, {%0,%1,%2,%3};"
        : "+f"(d0), "+f"(d1), "+f"(d2), "+f"(d3)
        : "r"(a0), "r"(a1), "r"(a2), "r"(a3), "r"(b0), "r"(b1));
}
// fp16-acc HMMA, accumulate into d
__device__ __forceinline__ void mma_h_acc(unsigned& d0, unsigned& d1,
                                          unsigned a0, unsigned a1, unsigned a2, unsigned a3,
                                          unsigned b0, unsigned b1) {
    asm volatile(
        "mma.sync.aligned.m16n8k16.row.col.f16.f16.f16.f16 "
        "{%0,%1}, {%2,%3,%4,%5}, {%6,%7}, {%0,%1};"
        : "+r"(d0), "+r"(d1)
        : "r"(a0), "r"(a1), "r"(a2), "r"(a3), "r"(b0), "r"(b1));
}
// fp16-acc HMMA, C = 0
__device__ __forceinline__ void mma_h_zero(unsigned& d0, unsigned& d1,
                                           unsigned a0, unsigned a1, unsigned a2, unsigned a3,
                                           unsigned b0, unsigned b1) {
    asm volatile(
        "mma.sync.aligned.m16n8k16.row.col.f16.f16.f16.f16 "
        "{%0,%1}, {%2,%3,%4,%5}, {%6,%7}, {%8,%8};"
        : "=r"(d0), "=r"(d1)
        : "r"(a0), "r"(a1), "r"(a2), "r"(a3), "r"(b0), "r"(b1), "r"(0u));
}
__device__ __forceinline__ void bar_group(int id) {
    asm volatile("bar.sync %0, 128;" :: "r"(id) : "memory");
}

// One CTA: 32 batch rows x one LSTM run. HMMA fp16 recurrent GEMM with fp16
// accumulators; latency-bound per ncu (tensor 32%, no pipe saturated), so
// occupancy raised to 3 CTAs/SM (launch_bounds regs<=84; only kc=0 B frags
// hoisted to fit). Final step fp32-acc MMA + fp32 epilogue, fp16 store.
__global__ __launch_bounds__(256, 3) void lstm_mma_kernel(
    const float* __restrict__ x0, const float* __restrict__ x1, const float* __restrict__ x2,
    const float* __restrict__ q00_wih, const float* __restrict__ q00_whh, const float* __restrict__ q00_b,
    const float* __restrict__ q01_wih, const float* __restrict__ q01_whh, const float* __restrict__ q01_b,
    const float* __restrict__ i00_wih, const float* __restrict__ i00_whh, const float* __restrict__ i00_b,
    const float* __restrict__ i01_wih, const float* __restrict__ i01_whh, const float* __restrict__ i01_b,
    const float* __restrict__ i02_wih, const float* __restrict__ i02_whh, const float* __restrict__ i02_b)
{
    extern __shared__ char smem[];
    const unsigned sb = smem_u32(smem);

    const float* x; const float* wih; const float* whh; const float* bias;
    __half* hout; int coloff;
    switch (blockIdx.y) {
        case 0:  x = x0; wih = q00_wih; whh = q00_whh; bias = q00_b; hout = g_hq; coloff = 0;   break;
        case 1:  x = x1; wih = q01_wih; whh = q01_whh; bias = q01_b; hout = g_hq; coloff = 64;  break;
        case 2:  x = x2; wih = q01_wih; whh = q01_whh; bias = q01_b; hout = g_hq; coloff = 128; break;
        case 3:  x = x0; wih = i00_wih; whh = i00_whh; bias = i00_b; hout = g_hi; coloff = 0;   break;
        case 4:  x = x1; wih = i01_wih; whh = i01_whh; bias = i01_b; hout = g_hi; coloff = 64;  break;
        default: x = x2; wih = i02_wih; whh = i02_whh; bias = i02_b; hout = g_hi; coloff = 128; break;
    }

    const int tid  = threadIdx.x;
    const int wid  = tid >> 5;
    const int lane = tid & 31;
    const int rg   = wid & 1;        // 16-row group
    const int gq   = wid >> 1;       // 64-gate quarter (0..3)
    const int g    = lane >> 2;
    const int tl   = lane & 3;
    const int r0g  = blockIdx.x * MROWS;

    // ---- stage whh fp16, permuted, 0.5-scaled for i/f/o (tg != 2) ----
    __half* ws = (__half*)(smem + OFF_WS);
    for (int idx = tid; idx < 256 * 64; idx += 256) {
        int go = idx >> 6, k = idx & 63;
        int tg = go >> 6, u = go & 63;
        int p  = (u & 3) * 2 + (tg & 1) + 8 * (tg >> 1) + 16 * (u >> 2);
        float sc = (tg == 2) ? 1.0f : 0.5f;
        ws[p * 72 + k] = __float2half(whh[idx] * sc);
    }
    // permuted {wih, b} table (final fp32 step only), same 0.5 scale for i/f/o
    {
        int go = tid;
        int tg = go >> 6, u = go & 63;
        int p  = (u & 3) * 2 + (tg & 1) + 8 * (tg >> 1) + 16 * (u >> 2);
        float sc = (tg == 2) ? 1.0f : 0.5f;
        ((float2*)(smem + OFF_WBS))[p] = make_float2(wih[go] * sc, bias[go] * sc);
    }
    // x tile [32][33]
    float* xs = (float*)(smem + OFF_XS);
    for (int idx = tid; idx < MROWS * TT; idx += 256) {
        int r = idx >> 5, tt = idx & 31;
        xs[r * 33 + tt] = x[(size_t)(r0g + r) * TT + tt];
    }
    __syncthreads();

    // per-lane ldmatrix addresses
    const int rowA  = rg * 16 + (lane & 7) + 8 * ((lane >> 3) & 1);
    const unsigned aoff = (unsigned)(rowA * 144 + (lane >> 4) * 16);
    const int rowBb = gq * 64 + (lane & 7) + 8 * (lane >> 4);
    const unsigned boff = (unsigned)(rowBb * 144 + ((lane >> 3) & 1) * 16);

    const int r0 = rg * 16 + g;       // this thread's rows
    const int r1 = r0 + 8;

    // hoist B fragments for kc = 0 only (reg budget for 3 CTAs/SM)
    unsigned bw[4][4];
    #pragma unroll
    for (int np = 0; np < 4; ++np)
        ldsm_x4(sb + OFF_WS + boff + (unsigned)(np * 16 * 144),
                bw[np][0], bw[np][1], bw[np][2], bw[np][3]);

    // hoisted half2 fold constants: per q, unit u = 16gq + 4q + tl
    __half2 w_if2[4], b_if2[4], w_go2[4], b_go2[4];
    #pragma unroll
    for (int q = 0; q < 4; ++q) {
        int u = 16 * gq + 4 * q + tl;
        w_if2[q] = __floats2half2_rn(0.5f * wih[u], 0.5f * wih[64 + u]);
        b_if2[q] = __floats2half2_rn(0.5f * bias[u], 0.5f * bias[64 + u]);
        w_go2[q] = __floats2half2_rn(wih[128 + u], 0.5f * wih[192 + u]);
        b_go2[q] = __floats2half2_rn(bias[128 + u], 0.5f * bias[192 + u]);
    }

    __half2 c2[4];
    #pragma unroll
    for (int i = 0; i < 4; ++i) c2[i] = __floats2half2_rn(0.f, 0.f);

    const __half2 h05   = __floats2half2_rn(0.5f, 0.5f);
    const __half2 m1_05 = __floats2half2_rn(1.0f, 0.5f);
    const __half2 a0_05 = __floats2half2_rn(0.0f, 0.5f);
    const int barid = 1 + rg;

    unsigned aif[4][2], ago[4][2];
    #pragma unroll
    for (int np = 0; np < 4; ++np) {
        aif[np][0] = aif[np][1] = 0u;
        ago[np][0] = ago[np][1] = 0u;
    }

    #pragma unroll 1
    for (int t = 0; t < TT - 1; ++t) {
        if (t > 0) {
            const unsigned rbase = sb + OFF_HS + ((unsigned)((t + 1) & 1)) * HS_BUF;
            #pragma unroll
            for (int kc = 0; kc < 4; ++kc) {
                unsigned ah0, ah1, ah2, ah3;
                ldsm_x4(rbase + aoff + kc * 32, ah0, ah1, ah2, ah3);
                #pragma unroll
                for (int np = 0; np < 4; ++np) {
                    unsigned b0, b1, b2, b3;
                    if (kc == 0) {
                        b0 = bw[np][0]; b1 = bw[np][1];
                        b2 = bw[np][2]; b3 = bw[np][3];
                    } else {
                        ldsm_x4(sb + OFF_WS + boff + (unsigned)(np * 16 * 144 + kc * 32),
                                b0, b1, b2, b3);
                    }
                    if (kc == 0) {
                        mma_h_zero(aif[np][0], aif[np][1], ah0, ah1, ah2, ah3, b0, b1);
                        mma_h_zero(ago[np][0], ago[np][1], ah0, ah1, ah2, ah3, b2, b3);
                    } else {
                        mma_h_acc(aif[np][0], aif[np][1], ah0, ah1, ah2, ah3, b0, b1);
                        mma_h_acc(ago[np][0], ago[np][1], ah0, ah1, ah2, ah3, b2, b3);
                    }
                }
            }
        }

        // pure-half2 epilogue
        __half* hw = (__half*)(smem + OFF_HS + (t & 1) * HS_BUF);
        __half2 xh0 = __half2half2(__float2half(xs[r0 * 33 + t]));
        __half2 xh1 = __half2half2(__float2half(xs[r1 * 33 + t]));
        #pragma unroll
        for (int q = 0; q < 4; ++q) {
            int u = 16 * gq + 4 * q + tl;
            __half2 if0 = __hadd2(*(__half2*)&aif[q][0], __hfma2(w_if2[q], xh0, b_if2[q]));
            __half2 if1 = __hadd2(*(__half2*)&aif[q][1], __hfma2(w_if2[q], xh1, b_if2[q]));
            __half2 go0 = __hadd2(*(__half2*)&ago[q][0], __hfma2(w_go2[q], xh0, b_go2[q]));
            __half2 go1 = __hadd2(*(__half2*)&ago[q][1], __hfma2(w_go2[q], xh1, b_go2[q]));

            __half2 sif0 = __hfma2(tanh2_ap(if0), h05, h05);
            __half2 sif1 = __hfma2(tanh2_ap(if1), h05, h05);
            __half2 gso0 = __hfma2(tanh2_ap(go0), m1_05, a0_05);
            __half2 gso1 = __hfma2(tanh2_ap(go1), m1_05, a0_05);

            __half2 si2 = __lows2half2(sif0, sif1);
            __half2 sf2 = __highs2half2(sif0, sif1);
            __half2 tg2 = __lows2half2(gso0, gso1);
            __half2 so2 = __highs2half2(gso0, gso1);
            c2[q] = __hfma2(sf2, c2[q], __hmul2(si2, tg2));
            __half2 h2v = __hmul2(so2, tanh2_ap(c2[q]));
            hw[r0 * 72 + u] = __low2half(h2v);
            hw[r1 * 72 + u] = __high2half(h2v);
        }
        bar_group(barid);
    }

    // ---- final step (t = TT-1): fp32-acc MMA + fp32 epilogue, fp16 store ----
    {
        const int t = TT - 1;
        float acc[32];
        #pragma unroll
        for (int i = 0; i < 32; ++i) acc[i] = 0.f;
        const unsigned rbase = sb + OFF_HS + ((unsigned)((t + 1) & 1)) * HS_BUF;
        #pragma unroll
        for (int kc = 0; kc < 4; ++kc) {
            unsigned ah0, ah1, ah2, ah3;
            ldsm_x4(rbase + aoff + kc * 32, ah0, ah1, ah2, ah3);
            #pragma unroll
            for (int np = 0; np < 4; ++np) {
                unsigned b0, b1, b2, b3;
                if (kc == 0) {
                    b0 = bw[np][0]; b1 = bw[np][1];
                    b2 = bw[np][2]; b3 = bw[np][3];
                } else {
                    ldsm_x4(sb + OFF_WS + boff + (unsigned)(np * 16 * 144 + kc * 32),
                            b0, b1, b2, b3);
                }
                float* e = acc + np * 8;
                mma16816(e[0], e[1], e[2], e[3], ah0, ah1, ah2, ah3, b0, b1);
                mma16816(e[4], e[5], e[6], e[7], ah0, ah1, ah2, ah3, b2, b3);
            }
        }
        const float4* wbs4 = (const float4*)(smem + OFF_WBS);
        float xv0 = xs[r0 * 33 + t];
        float xv1 = xs[r1 * 33 + t];
        #pragma unroll
        for (int q = 0; q < 4; ++q) {
            int pq = 16 * (gq * 4 + q) + 2 * tl;
            float4 wif = wbs4[pq >> 1];
            float4 wgo = wbs4[(pq >> 1) + 4];
            int u = 16 * gq + 4 * q + tl;
            float2 cf = __half22float2(c2[q]);
            #pragma unroll
            for (int rowj = 0; rowj < 2; ++rowj) {
                float xv = rowj ? xv1 : xv0;
                float iv = acc[8 * q + rowj * 2 + 0] + fmaf(wif.x, xv, wif.y);
                float fv = acc[8 * q + rowj * 2 + 1] + fmaf(wif.z, xv, wif.w);
                float gv = acc[8 * q + 4 + rowj * 2 + 0] + fmaf(wgo.x, xv, wgo.y);
                float ov = acc[8 * q + 4 + rowj * 2 + 1] + fmaf(wgo.z, xv, wgo.w);
                float si = fmaf(0.5f, tanh_ap(iv), 0.5f);
                float sf = fmaf(0.5f, tanh_ap(fv), 0.5f);
                float so = fmaf(0.5f, tanh_ap(ov), 0.5f);
                float cold = rowj ? cf.y : cf.x;
                float cc = sf * cold + si * tanh_ap(gv);
                float h = so * tanh_ap(cc);
                int row = rowj ? r1 : r0;
                hout[(size_t)(r0g + row) * 192 + coloff + u] = __float2half(h);
            }
        }
    }
}

// Head: grid (128, 2): 32 rows x one branch per CTA, ~60KB smem -> 3 CTAs/SM.
// A staged by uint4 copy from fp16 hidden states. GEMM1 on HMMA fp16/fp32-acc.
__global__ __launch_bounds__(256) void head_kernel(
    const float* __restrict__ s2,
    const float* __restrict__ q03_w, const float* __restrict__ q03_b,
    const float* __restrict__ q1_w,  const float* __restrict__ q1_b,
    const float* __restrict__ q2_w,  const float* __restrict__ q2_b,
    const float* __restrict__ i03_w, const float* __restrict__ i03_b,
    const float* __restrict__ i1_w,  const float* __restrict__ i1_b,
    const float* __restrict__ i2_w,  const float* __restrict__ i2_b,
    float* __restrict__ out)
{
    extern __shared__ char smh[];
    const unsigned sbh = smem_u32(smh);
    __half* Ah = (__half*)(smh + H_AH);       // [32][264] halves
    __half* Bh = (__half*)(smh + H_BH);       // [64][264]
    float* qb  = (float*)(smh + H_QB);        // [32][66]
    float* ib  = (float*)(smh + H_IB);        // [32][8]

    const int tid  = threadIdx.x;
    const int wid  = tid >> 5;
    const int lane = tid & 31;
    const int row0 = blockIdx.x * 32;
    const int br   = blockIdx.y;

    const __half* gh = br ? g_hi  : g_hq;
    const float* w03 = br ? i03_w : q03_w;
    const float* b03 = br ? i03_b : q03_b;
    const float* w1  = br ? i1_w  : q1_w;
    const float* b1  = br ? i1_b  : q1_b;
    const float* w2  = br ? i2_w  : q2_w;
    const float* b2  = br ? i2_b  : q2_b;

    // stage A cols [0:192): raw uint4 copy of fp16 hidden states (24 uint4/row)
    for (int idx = tid; idx < 32 * 24; idx += 256) {
        int r = idx / 24, c8 = idx - r * 24;
        uint4 v = *(const uint4*)&gh[(size_t)(row0 + r) * 192 + c8 * 8];
        *(uint4*)&Ah[r * 264 + c8 * 8] = v;
    }
    // stage A cols [192:256): relu(s2 @ w03 + b03)
    for (int idx = tid; idx < 32 * 64; idx += 256) {
        int r = idx >> 6, u = idx & 63;
        const float* s = &s2[(row0 + r) * 3];
        float a = b03[u] + s[0] * w03[u * 3] + s[1] * w03[u * 3 + 1] + s[2] * w03[u * 3 + 2];
        Ah[r * 264 + 192 + u] = __float2half(fmaxf(a, 0.f));
    }
    // stage B = w1 [64 u][256 k] (float4 vectorized, fp32 -> fp16)
    for (int idx = tid; idx < 64 * 64; idx += 256) {
        int u = idx >> 6, k4 = idx & 63;
        float4 v = *(const float4*)&w1[u * 256 + k4 * 4];
        __half2* d = (__half2*)&Bh[u * 264 + k4 * 4];
        d[0] = __floats2half2_rn(v.x, v.y);
        d[1] = __floats2half2_rn(v.z, v.w);
    }
    __syncthreads();

    // GEMM1: warp (mt, nq): rows mt*16..+15, cols nq*16..+15
    const int mt = wid & 1;
    const int nq = wid >> 1;
    const int g  = lane >> 2;
    const int tl = lane & 3;
    const unsigned abase = sbh + H_AH +
        (unsigned)((mt * 16 + (lane & 7) + 8 * ((lane >> 3) & 1)) * 528 + (lane >> 4) * 16);
    const unsigned bbase = sbh + H_BH +
        (unsigned)((nq * 16 + (lane & 7) + 8 * (lane >> 4)) * 528 + ((lane >> 3) & 1) * 16);

    float acc[8];
    #pragma unroll
    for (int i = 0; i < 8; ++i) acc[i] = 0.f;

    #pragma unroll
    for (int kc = 0; kc < 16; ++kc) {
        unsigned a0, a1, a2, a3, b0, b1, b2, b3;
        ldsm_x4(abase + kc * 32, a0, a1, a2, a3);
        ldsm_x4(bbase + kc * 32, b0, b1, b2, b3);
        mma16816(acc[0], acc[1], acc[2], acc[3], a0, a1, a2, a3, b0, b1);
        mma16816(acc[4], acc[5], acc[6], acc[7], a0, a1, a2, a3, b2, b3);
    }

    // relu + bias -> qb
    const int r0h = mt * 16 + g;
    const int r1h = r0h + 8;
    #pragma unroll
    for (int nt = 0; nt < 2; ++nt) {
        int col = nq * 16 + nt * 8 + tl * 2;
        float bb0 = b1[col], bb1 = b1[col + 1];
        qb[r0h * 66 + col]     = fmaxf(acc[nt * 4 + 0] + bb0, 0.f);
        qb[r0h * 66 + col + 1] = fmaxf(acc[nt * 4 + 1] + bb1, 0.f);
        qb[r1h * 66 + col]     = fmaxf(acc[nt * 4 + 2] + bb0, 0.f);
        qb[r1h * 66 + col + 1] = fmaxf(acc[nt * 4 + 3] + bb1, 0.f);
    }
    __syncthreads();

    // GEMV2: 32 rows x 6 outputs
    if (tid < 32 * AA) {
        int r = tid / AA;
        int a = tid - r * AA;
        float acc2 = b2[a];
        #pragma unroll 8
        for (int k = 0; k < 64; ++k)
            acc2 = fmaf(w2[a * 64 + k], qb[r * 66 + k], acc2);
        if (br == 0) out[(row0 + r) * AA + a] = acc2;        // q (no relu)
        else         ib[r * 8 + a] = fmaxf(acc2, 0.f);       // i vec
    }
    if (br == 1) {
        __syncthreads();
        if (tid < 32) {
            int r = tid;
            float m = ib[r * 8];
            #pragma unroll
            for (int j = 1; j < AA; ++j) m = fmaxf(m, ib[r * 8 + j]);
            float s = 0.f;
            #pragma unroll
            for (int j = 0; j < AA; ++j) s += __expf(ib[r * 8 + j] - m);
            float lse = m + __logf(s);
            #pragma unroll
            for (int j = 0; j < AA; ++j) {
                float iv = ib[r * 8 + j];
                out[BB * AA + (row0 + r) * AA + j]     = iv - lse;
                out[2 * BB * AA + (row0 + r) * AA + j] = iv;
            }
        }
    }
}

extern "C" void kernel_launch(void* const* d_in, const int* in_sizes, int n_in,
                              void* d_out, int out_size)
{
    const float* x0 = (const float*)d_in[0];
    const float* x1 = (const float*)d_in[1];
    const float* x2 = (const float*)d_in[2];
    const float* s2 = (const float*)d_in[3];
    const float* q00_wih = (const float*)d_in[4];
    const float* q00_whh = (const float*)d_in[5];
    const float* q00_b   = (const float*)d_in[6];
    const float* q01_wih = (const float*)d_in[7];
    const float* q01_whh = (const float*)d_in[8];
    const float* q01_b   = (const float*)d_in[9];
    const float* i00_wih = (const float*)d_in[10];
    const float* i00_whh = (const float*)d_in[11];
    const float* i00_b   = (const float*)d_in[12];
    const float* i01_wih = (const float*)d_in[13];
    const float* i01_whh = (const float*)d_in[14];
    const float* i01_b   = (const float*)d_in[15];
    const float* i02_wih = (const float*)d_in[16];
    const float* i02_whh = (const float*)d_in[17];
    const float* i02_b   = (const float*)d_in[18];
    const float* q03_w = (const float*)d_in[19];
    const float* q03_b = (const float*)d_in[20];
    const float* q1_w  = (const float*)d_in[21];
    const float* q1_b  = (const float*)d_in[22];
    const float* q2_w  = (const float*)d_in[23];
    const float* q2_b  = (const float*)d_in[24];
    const float* i03_w = (const float*)d_in[25];
    const float* i03_b = (const float*)d_in[26];
    const float* i1_w  = (const float*)d_in[27];
    const float* i1_b  = (const float*)d_in[28];
    const float* i2_w  = (const float*)d_in[29];
    const float* i2_b  = (const float*)d_in[30];
    float* out = (float*)d_out;

    cudaFuncSetAttribute(lstm_mma_kernel, cudaFuncAttributeMaxDynamicSharedMemorySize, LSTM_SMEM_BYTES);
    cudaFuncSetAttribute(head_kernel, cudaFuncAttributeMaxDynamicSharedMemorySize, HEAD_SMEM_BYTES);

    dim3 grid(BB / MROWS, 6);   // 128 batch tiles x 6 LSTM runs = 768 CTAs, 3/SM
    lstm_mma_kernel<<<grid, 256, LSTM_SMEM_BYTES>>>(
        x0, x1, x2,
        q00_wih, q00_whh, q00_b,
        q01_wih, q01_whh, q01_b,
        i00_wih, i00_whh, i00_b,
        i01_wih, i01_whh, i01_b,
        i02_wih, i02_whh, i02_b);

    head_kernel<<<dim3(BB / 32, 2), 256, HEAD_SMEM_BYTES>>>(
        s2,
        q03_w, q03_b, q1_w, q1_b, q2_w, q2_b,
        i03_w, i03_b, i1_w, i1_b, i2_w, i2_b,
        out);
}

// round 17
// speedup vs baseline: 1.0986x; 1.0587x over previous
#include <cuda_runtime.h>
#include <cuda_fp16.h>

// Problem constants
#define HH    64
#define TT    32
#define BB    4096
#define AA    6
#define MROWS 32        // batch rows per lstm CTA

// lstm smem layout (bytes). Weight rows padded to 144B (72 halves).
#define OFF_WS  0                    // Ws [256][72] half, permuted p = 64*(u>>4)+16*tg+(u&15)
#define OFF_HS  36864                // hs double buffer: 2 x [32][72] half
#define HS_BUF  4608                 // bytes per h buffer
#define OFF_XS  46080                // half [TT][32], t-major (transposed)
#define LSTM_SMEM_BYTES (OFF_XS + TT * 32 * 2)   // 48128

// head kernel (HMMA, 32 rows/CTA): grid (128, 2) = 256 CTAs.
#define H_AH 0                       // A fp16 [32][264]
#define H_BH 16896                   // B fp16 [64][264]
#define H_QB 50688                   // qb fp32 [32][66]
#define H_IB 59136                   // ib fp32 [32][8]
#define HEAD_SMEM_BYTES (H_IB + 1536)

// scratch: final hidden states fp16, [B][192] (3 LSTM outputs per branch)
__device__ __half g_hq[BB * 192];
__device__ __half g_hi[BB * 192];

__device__ __forceinline__ float tanh_ap(float x) {
    float y;
    asm("tanh.approx.f32 %0, %1;" : "=f"(y) : "f"(x));
    return y;
}
__device__ __forceinline__ __half2 tanh2_ap(__half2 x) {
    __half2 y;
    asm("tanh.approx.f16x2 %0, %1;" : "=r"(*(unsigned*)&y) : "r"(*(unsigned*)&x));
    return y;
}

__device__ __forceinline__ unsigned smem_u32(const void* p) {
    unsigned a;
    asm("{ .reg .u64 t; cvta.to.shared.u64 t, %1; cvt.u32.u64 %0, t; }" : "=r"(a) : "l"(p));
    return a;
}
__device__ __forceinline__ void ldsm_x4(unsigned addr, unsigned& r0, unsigned& r1,
                                        unsigned& r2, unsigned& r3) {
    asm volatile("ldmatrix.sync.aligned.m8n8.x4.shared.b16 {%0,%1,%2,%3}, [%4];"
                 : "=r"(r0), "=r"(r1), "=r"(r2), "=r"(r3) : "r"(addr));
}
// fp32-acc HMMA
__device__ __forceinline__ void mma16816(float& d0, float& d1, float& d2, float& d3,
                                         unsigned a0, unsigned a1, unsigned a2, unsigned a3,
                                         unsigned b0, unsigned b1) {
    asm volatile(
        "mma.sync.aligned.m16n8k16.row.col.f32.f16.f16.f32 "
        "{%0,%1,%2,%3}, {%4,%5,%6,%7}, {%8,%9}, {%0,%1,%2,%3};"
        : "+f"(d0), "+f"(d1), "+f"(d2), "+f"(d3)
        : "r"(a0), "r"(a1), "r"(a2), "r"(a3), "r"(b0), "r"(b1));
}
// fp16-acc HMMA, accumulate into d
__device__ __forceinline__ void mma_h_acc(unsigned& d0, unsigned& d1,
                                          unsigned a0, unsigned a1, unsigned a2, unsigned a3,
                                          unsigned b0, unsigned b1) {
    asm volatile(
        "mma.sync.aligned.m16n8k16.row.col.f16.f16.f16.f16 "
        "{%0,%1}, {%2,%3,%4,%5}, {%6,%7}, {%0,%1};"
        : "+r"(d0), "+r"(d1)
        : "r"(a0), "r"(a1), "r"(a2), "r"(a3), "r"(b0), "r"(b1));
}
// fp16-acc HMMA, C = 0
__device__ __forceinline__ void mma_h_zero(unsigned& d0, unsigned& d1,
                                           unsigned a0, unsigned a1, unsigned a2, unsigned a3,
                                           unsigned b0, unsigned b1) {
    asm volatile(
        "mma.sync.aligned.m16n8k16.row.col.f16.f16.f16.f16 "
        "{%0,%1}, {%2,%3,%4,%5}, {%6,%7}, {%8,%8};"
        : "=r"(d0), "=r"(d1)
        : "r"(a0), "r"(a1), "r"(a2), "r"(a3), "r"(b0), "r"(b1), "r"(0u));
}
__device__ __forceinline__ void bar_group(int id) {
    asm volatile("bar.sync %0, 128;" :: "r"(id) : "memory");
}

// One CTA: 32 batch rows x one LSTM run. OPERAND-SWAPPED HMMA: A = weights
// (M = gates, register-resident: 16 fragments loaded once), B = h (N = rows,
// 4 ldsm.x4 per step). This removes the per-step weight re-read that made the
// old version SMEM-crossbar-bound (80KB -> 16KB per CTA-step). Permutation
// p = 64*(u>>4) + 16*tg + (u&15): each m-tile is one gate type, so D comes
// out as half2-over-row-pairs per (unit, type) -> pure-half2 epilogue with
// fp16 cell state. i/f/o weights pre-scaled 0.5 (sigmoid = 0.5*tanh+0.5).
// Final step: fp32-acc MMA + fp32 epilogue, fp16 store.
__global__ __launch_bounds__(256, 2) void lstm_mma_kernel(
    const float* __restrict__ x0, const float* __restrict__ x1, const float* __restrict__ x2,
    const float* __restrict__ q00_wih, const float* __restrict__ q00_whh, const float* __restrict__ q00_b,
    const float* __restrict__ q01_wih, const float* __restrict__ q01_whh, const float* __restrict__ q01_b,
    const float* __restrict__ i00_wih, const float* __restrict__ i00_whh, const float* __restrict__ i00_b,
    const float* __restrict__ i01_wih, const float* __restrict__ i01_whh, const float* __restrict__ i01_b,
    const float* __restrict__ i02_wih, const float* __restrict__ i02_whh, const float* __restrict__ i02_b)
{
    extern __shared__ char smem[];
    const unsigned sb = smem_u32(smem);

    const float* x; const float* wih; const float* whh; const float* bias;
    __half* hout; int coloff;
    switch (blockIdx.y) {
        case 0:  x = x0; wih = q00_wih; whh = q00_whh; bias = q00_b; hout = g_hq; coloff = 0;   break;
        case 1:  x = x1; wih = q01_wih; whh = q01_whh; bias = q01_b; hout = g_hq; coloff = 64;  break;
        case 2:  x = x2; wih = q01_wih; whh = q01_whh; bias = q01_b; hout = g_hq; coloff = 128; break;
        case 3:  x = x0; wih = i00_wih; whh = i00_whh; bias = i00_b; hout = g_hi; coloff = 0;   break;
        case 4:  x = x1; wih = i01_wih; whh = i01_whh; bias = i01_b; hout = g_hi; coloff = 64;  break;
        default: x = x2; wih = i02_wih; whh = i02_whh; bias = i02_b; hout = g_hi; coloff = 128; break;
    }

    const int tid  = threadIdx.x;
    const int wid  = tid >> 5;
    const int lane = tid & 31;
    const int rg   = wid & 1;        // 16-row group
    const int gq   = wid >> 1;       // 16-unit quarter (64 permuted gates)
    const int g    = lane >> 2;
    const int tl   = lane & 3;
    const int r0g  = blockIdx.x * MROWS;

    // ---- stage whh fp16, permuted p = 64*(u>>4) + 16*tg + (u&15),
    //      0.5-scaled for i/f/o (tg != 2) ----
    __half* ws = (__half*)(smem + OFF_WS);
    for (int idx = tid; idx < 256 * 64; idx += 256) {
        int go = idx >> 6, k = idx & 63;
        int tg = go >> 6, u = go & 63;
        int p  = 64 * (u >> 4) + 16 * tg + (u & 15);
        float sc = (tg == 2) ? 1.0f : 0.5f;
        ws[p * 72 + k] = __float2half(whh[idx] * sc);
    }
    // x tile transposed fp16: xsh[t][r]
    __half* xsh = (__half*)(smem + OFF_XS);
    for (int idx = tid; idx < MROWS * TT; idx += 256) {
        int r = idx >> 5, tt = idx & 31;
        xsh[tt * 32 + r] = __float2half(x[(size_t)(r0g + r) * TT + tt]);
    }
    __syncthreads();

    // ---- hoist ALL weight A-fragments into registers (static) ----
    // aw[mt][kc][4]: m-tile = gate type mt, rows 64*gq + 16*mt + ...
    const unsigned arow = (unsigned)((lane & 7) + 8 * ((lane >> 3) & 1));
    const unsigned acol = (unsigned)((lane >> 4) * 16);
    unsigned aw[4][4][4];
    #pragma unroll
    for (int mt = 0; mt < 4; ++mt)
        #pragma unroll
        for (int kc = 0; kc < 4; ++kc)
            ldsm_x4(sb + OFF_WS + (unsigned)((64 * gq + 16 * mt) + arow) * 144
                        + acol + kc * 32,
                    aw[mt][kc][0], aw[mt][kc][1], aw[mt][kc][2], aw[mt][kc][3]);

    // per-lane B (h) ldsm address pattern: rows rg*16 + ...
    const unsigned hpat = (unsigned)((rg * 16 + (lane & 7) + 8 * (lane >> 4)) * 144
                                     + ((lane >> 3) & 1) * 16);

    // fold constants: wd/bd[type][un], unit u = 16*gq + g + 8*un, duplicated half2
    __half2 wd[4][2], bd[4][2];
    #pragma unroll
    for (int t = 0; t < 4; ++t) {
        float sc = (t == 2) ? 1.0f : 0.5f;
        #pragma unroll
        for (int un = 0; un < 2; ++un) {
            int u = 16 * gq + g + 8 * un;
            wd[t][un] = __half2half2(__float2half(wih[t * 64 + u] * sc));
            bd[t][un] = __half2half2(__float2half(bias[t * 64 + u] * sc));
        }
    }

    __half2 c2[2][2];   // [un][nt]
    #pragma unroll
    for (int a = 0; a < 2; ++a)
        #pragma unroll
        for (int b = 0; b < 2; ++b) c2[a][b] = __floats2half2_rn(0.f, 0.f);

    const __half2 h05 = __floats2half2_rn(0.5f, 0.5f);
    const int barid = 1 + rg;
    const int xbase = rg * 16 + 2 * tl;

    // D accumulators: acc[mt][nt][reg] ; reg 0 = unit g, reg 1 = unit g+8
    unsigned acc[4][2][2];
    #pragma unroll
    for (int mt = 0; mt < 4; ++mt)
        #pragma unroll
        for (int nt = 0; nt < 2; ++nt) { acc[mt][nt][0] = 0u; acc[mt][nt][1] = 0u; }

    #pragma unroll 1
    for (int t = 0; t < TT - 1; ++t) {
        if (t > 0) {
            const unsigned hb = sb + OFF_HS + ((unsigned)((t + 1) & 1)) * HS_BUF + hpat;
            #pragma unroll
            for (int kc = 0; kc < 4; ++kc) {
                unsigned b0, b1, b2, b3;
                ldsm_x4(hb + kc * 32, b0, b1, b2, b3);
                #pragma unroll
                for (int mt = 0; mt < 4; ++mt) {
                    if (kc == 0) {
                        mma_h_zero(acc[mt][0][0], acc[mt][0][1],
                                   aw[mt][0][0], aw[mt][0][1], aw[mt][0][2], aw[mt][0][3],
                                   b0, b1);
                        mma_h_zero(acc[mt][1][0], acc[mt][1][1],
                                   aw[mt][0][0], aw[mt][0][1], aw[mt][0][2], aw[mt][0][3],
                                   b2, b3);
                    } else {
                        mma_h_acc(acc[mt][0][0], acc[mt][0][1],
                                  aw[mt][kc][0], aw[mt][kc][1], aw[mt][kc][2], aw[mt][kc][3],
                                  b0, b1);
                        mma_h_acc(acc[mt][1][0], acc[mt][1][1],
                                  aw[mt][kc][0], aw[mt][kc][1], aw[mt][kc][2], aw[mt][kc][3],
                                  b2, b3);
                    }
                }
            }
        }

        // pure-half2 epilogue: gates arrive per-type as half2 over row pairs
        __half* hw = (__half*)(smem + OFF_HS + (t & 1) * HS_BUF);
        __half2 xh0 = *(const __half2*)&xsh[t * 32 + xbase];
        __half2 xh1 = *(const __half2*)&xsh[t * 32 + xbase + 8];
        #pragma unroll
        for (int un = 0; un < 2; ++un) {
            int u = 16 * gq + g + 8 * un;
            #pragma unroll
            for (int nt = 0; nt < 2; ++nt) {
                __half2 xh = nt ? xh1 : xh0;
                __half2 i2 = __hadd2(*(__half2*)&acc[0][nt][un], __hfma2(wd[0][un], xh, bd[0][un]));
                __half2 f2 = __hadd2(*(__half2*)&acc[1][nt][un], __hfma2(wd[1][un], xh, bd[1][un]));
                __half2 g2 = __hadd2(*(__half2*)&acc[2][nt][un], __hfma2(wd[2][un], xh, bd[2][un]));
                __half2 o2 = __hadd2(*(__half2*)&acc[3][nt][un], __hfma2(wd[3][un], xh, bd[3][un]));

                __half2 si = __hfma2(tanh2_ap(i2), h05, h05);
                __half2 sf = __hfma2(tanh2_ap(f2), h05, h05);
                __half2 so = __hfma2(tanh2_ap(o2), h05, h05);
                __half2 tg2 = tanh2_ap(g2);
                c2[un][nt] = __hfma2(sf, c2[un][nt], __hmul2(si, tg2));
                __half2 h2v = __hmul2(so, tanh2_ap(c2[un][nt]));
                int r = rg * 16 + 2 * tl + 8 * nt;
                hw[r * 72 + u]       = __low2half(h2v);
                hw[(r + 1) * 72 + u] = __high2half(h2v);
            }
        }
        bar_group(barid);   // group-local: new h visible; prior reads complete
    }

    // ---- final step (t = TT-1): fp32-acc MMA + fp32 epilogue, fp16 store ----
    {
        const int t = TT - 1;
        float af[4][2][4];
        #pragma unroll
        for (int mt = 0; mt < 4; ++mt)
            #pragma unroll
            for (int nt = 0; nt < 2; ++nt)
                #pragma unroll
                for (int i = 0; i < 4; ++i) af[mt][nt][i] = 0.f;

        const unsigned hb = sb + OFF_HS + ((unsigned)((t + 1) & 1)) * HS_BUF + hpat;
        #pragma unroll
        for (int kc = 0; kc < 4; ++kc) {
            unsigned b0, b1, b2, b3;
            ldsm_x4(hb + kc * 32, b0, b1, b2, b3);
            #pragma unroll
            for (int mt = 0; mt < 4; ++mt) {
                mma16816(af[mt][0][0], af[mt][0][1], af[mt][0][2], af[mt][0][3],
                         aw[mt][kc][0], aw[mt][kc][1], aw[mt][kc][2], aw[mt][kc][3],
                         b0, b1);
                mma16816(af[mt][1][0], af[mt][1][1], af[mt][1][2], af[mt][1][3],
                         aw[mt][kc][0], aw[mt][kc][1], aw[mt][kc][2], aw[mt][kc][3],
                         b2, b3);
            }
        }
        #pragma unroll
        for (int un = 0; un < 2; ++un) {
            int u = 16 * gq + g + 8 * un;
            float wi = __half2float(__low2half(wd[0][un])), bi = __half2float(__low2half(bd[0][un]));
            float wf = __half2float(__low2half(wd[1][un])), bf = __half2float(__low2half(bd[1][un]));
            float wg = __half2float(__low2half(wd[2][un])), bg = __half2float(__low2half(bd[2][un]));
            float wo = __half2float(__low2half(wd[3][un])), bo = __half2float(__low2half(bd[3][un]));
            #pragma unroll
            for (int nt = 0; nt < 2; ++nt) {
                float2 cf = __half22float2(c2[un][nt]);
                #pragma unroll
                for (int rowj = 0; rowj < 2; ++rowj) {
                    int r = rg * 16 + 2 * tl + 8 * nt + rowj;
                    float xv = __half2float(xsh[t * 32 + r]);
                    int di = un * 2 + rowj;
                    float iv = af[0][nt][di] + fmaf(wi, xv, bi);
                    float fv = af[1][nt][di] + fmaf(wf, xv, bf);
                    float gv = af[2][nt][di] + fmaf(wg, xv, bg);
                    float ov = af[3][nt][di] + fmaf(wo, xv, bo);
                    float si = fmaf(0.5f, tanh_ap(iv), 0.5f);
                    float sf = fmaf(0.5f, tanh_ap(fv), 0.5f);
                    float so = fmaf(0.5f, tanh_ap(ov), 0.5f);
                    float cold = rowj ? cf.y : cf.x;
                    float cc = sf * cold + si * tanh_ap(gv);
                    float h = so * tanh_ap(cc);
                    hout[(size_t)(r0g + r) * 192 + coloff + u] = __float2half(h);
                }
            }
        }
    }
}

// Head: grid (128, 2): 32 rows x one branch per CTA. A staged by uint4 copy
// from fp16 hidden states. GEMM1 on HMMA fp16/fp32-acc.
__global__ __launch_bounds__(256) void head_kernel(
    const float* __restrict__ s2,
    const float* __restrict__ q03_w, const float* __restrict__ q03_b,
    const float* __restrict__ q1_w,  const float* __restrict__ q1_b,
    const float* __restrict__ q2_w,  const float* __restrict__ q2_b,
    const float* __restrict__ i03_w, const float* __restrict__ i03_b,
    const float* __restrict__ i1_w,  const float* __restrict__ i1_b,
    const float* __restrict__ i2_w,  const float* __restrict__ i2_b,
    float* __restrict__ out)
{
    extern __shared__ char smh[];
    const unsigned sbh = smem_u32(smh);
    __half* Ah = (__half*)(smh + H_AH);       // [32][264] halves
    __half* Bh = (__half*)(smh + H_BH);       // [64][264]
    float* qb  = (float*)(smh + H_QB);        // [32][66]
    float* ib  = (float*)(smh + H_IB);        // [32][8]

    const int tid  = threadIdx.x;
    const int wid  = tid >> 5;
    const int lane = tid & 31;
    const int row0 = blockIdx.x * 32;
    const int br   = blockIdx.y;

    const __half* gh = br ? g_hi  : g_hq;
    const float* w03 = br ? i03_w : q03_w;
    const float* b03 = br ? i03_b : q03_b;
    const float* w1  = br ? i1_w  : q1_w;
    const float* b1  = br ? i1_b  : q1_b;
    const float* w2  = br ? i2_w  : q2_w;
    const float* b2  = br ? i2_b  : q2_b;

    // stage A cols [0:192): raw uint4 copy of fp16 hidden states (24 uint4/row)
    for (int idx = tid; idx < 32 * 24; idx += 256) {
        int r = idx / 24, c8 = idx - r * 24;
        uint4 v = *(const uint4*)&gh[(size_t)(row0 + r) * 192 + c8 * 8];
        *(uint4*)&Ah[r * 264 + c8 * 8] = v;
    }
    // stage A cols [192:256): relu(s2 @ w03 + b03)
    for (int idx = tid; idx < 32 * 64; idx += 256) {
        int r = idx >> 6, u = idx & 63;
        const float* s = &s2[(row0 + r) * 3];
        float a = b03[u] + s[0] * w03[u * 3] + s[1] * w03[u * 3 + 1] + s[2] * w03[u * 3 + 2];
        Ah[r * 264 + 192 + u] = __float2half(fmaxf(a, 0.f));
    }
    // stage B = w1 [64 u][256 k] (float4 vectorized, fp32 -> fp16)
    for (int idx = tid; idx < 64 * 64; idx += 256) {
        int u = idx >> 6, k4 = idx & 63;
        float4 v = *(const float4*)&w1[u * 256 + k4 * 4];
        __half2* d = (__half2*)&Bh[u * 264 + k4 * 4];
        d[0] = __floats2half2_rn(v.x, v.y);
        d[1] = __floats2half2_rn(v.z, v.w);
    }
    __syncthreads();

    // GEMM1: warp (mt, nq): rows mt*16..+15, cols nq*16..+15
    const int mt = wid & 1;
    const int nq = wid >> 1;
    const int g  = lane >> 2;
    const int tl = lane & 3;
    const unsigned abase = sbh + H_AH +
        (unsigned)((mt * 16 + (lane & 7) + 8 * ((lane >> 3) & 1)) * 528 + (lane >> 4) * 16);
    const unsigned bbase = sbh + H_BH +
        (unsigned)((nq * 16 + (lane & 7) + 8 * (lane >> 4)) * 528 + ((lane >> 3) & 1) * 16);

    float acc[8];
    #pragma unroll
    for (int i = 0; i < 8; ++i) acc[i] = 0.f;

    #pragma unroll
    for (int kc = 0; kc < 16; ++kc) {
        unsigned a0, a1, a2, a3, b0, b1, b2, b3;
        ldsm_x4(abase + kc * 32, a0, a1, a2, a3);
        ldsm_x4(bbase + kc * 32, b0, b1, b2, b3);
        mma16816(acc[0], acc[1], acc[2], acc[3], a0, a1, a2, a3, b0, b1);
        mma16816(acc[4], acc[5], acc[6], acc[7], a0, a1, a2, a3, b2, b3);
    }

    // relu + bias -> qb
    const int r0h = mt * 16 + g;
    const int r1h = r0h + 8;
    #pragma unroll
    for (int nt = 0; nt < 2; ++nt) {
        int col = nq * 16 + nt * 8 + tl * 2;
        float bb0 = b1[col], bb1 = b1[col + 1];
        qb[r0h * 66 + col]     = fmaxf(acc[nt * 4 + 0] + bb0, 0.f);
        qb[r0h * 66 + col + 1] = fmaxf(acc[nt * 4 + 1] + bb1, 0.f);
        qb[r1h * 66 + col]     = fmaxf(acc[nt * 4 + 2] + bb0, 0.f);
        qb[r1h * 66 + col + 1] = fmaxf(acc[nt * 4 + 3] + bb1, 0.f);
    }
    __syncthreads();

    // GEMV2: 32 rows x 6 outputs
    if (tid < 32 * AA) {
        int r = tid / AA;
        int a = tid - r * AA;
        float acc2 = b2[a];
        #pragma unroll 8
        for (int k = 0; k < 64; ++k)
            acc2 = fmaf(w2[a * 64 + k], qb[r * 66 + k], acc2);
        if (br == 0) out[(row0 + r) * AA + a] = acc2;        // q (no relu)
        else         ib[r * 8 + a] = fmaxf(acc2, 0.f);       // i vec
    }
    if (br == 1) {
        __syncthreads();
        if (tid < 32) {
            int r = tid;
            float m = ib[r * 8];
            #pragma unroll
            for (int j = 1; j < AA; ++j) m = fmaxf(m, ib[r * 8 + j]);
            float s = 0.f;
            #pragma unroll
            for (int j = 0; j < AA; ++j) s += __expf(ib[r * 8 + j] - m);
            float lse = m + __logf(s);
            #pragma unroll
            for (int j = 0; j < AA; ++j) {
                float iv = ib[r * 8 + j];
                out[BB * AA + (row0 + r) * AA + j]     = iv - lse;
                out[2 * BB * AA + (row0 + r) * AA + j] = iv;
            }
        }
    }
}

extern "C" void kernel_launch(void* const* d_in, const int* in_sizes, int n_in,
                              void* d_out, int out_size)
{
    const float* x0 = (const float*)d_in[0];
    const float* x1 = (const float*)d_in[1];
    const float* x2 = (const float*)d_in[2];
    const float* s2 = (const float*)d_in[3];
    const float* q00_wih = (const float*)d_in[4];
    const float* q00_whh = (const float*)d_in[5];
    const float* q00_b   = (const float*)d_in[6];
    const float* q01_wih = (const float*)d_in[7];
    const float* q01_whh = (const float*)d_in[8];
    const float* q01_b   = (const float*)d_in[9];
    const float* i00_wih = (const float*)d_in[10];
    const float* i00_whh = (const float*)d_in[11];
    const float* i00_b   = (const float*)d_in[12];
    const float* i01_wih = (const float*)d_in[13];
    const float* i01_whh = (const float*)d_in[14];
    const float* i01_b   = (const float*)d_in[15];
    const float* i02_wih = (const float*)d_in[16];
    const float* i02_whh = (const float*)d_in[17];
    const float* i02_b   = (const float*)d_in[18];
    const float* q03_w = (const float*)d_in[19];
    const float* q03_b = (const float*)d_in[20];
    const float* q1_w  = (const float*)d_in[21];
    const float* q1_b  = (const float*)d_in[22];
    const float* q2_w  = (const float*)d_in[23];
    const float* q2_b  = (const float*)d_in[24];
    const float* i03_w = (const float*)d_in[25];
    const float* i03_b = (const float*)d_in[26];
    const float* i1_w  = (const float*)d_in[27];
    const float* i1_b  = (const float*)d_in[28];
    const float* i2_w  = (const float*)d_in[29];
    const float* i2_b  = (const float*)d_in[30];
    float* out = (float*)d_out;

    cudaFuncSetAttribute(lstm_mma_kernel, cudaFuncAttributeMaxDynamicSharedMemorySize, LSTM_SMEM_BYTES);
    cudaFuncSetAttribute(head_kernel, cudaFuncAttributeMaxDynamicSharedMemorySize, HEAD_SMEM_BYTES);

    dim3 grid(BB / MROWS, 6);   // 128 batch tiles x 6 LSTM runs = 768 CTAs
    lstm_mma_kernel<<<grid, 256, LSTM_SMEM_BYTES>>>(
        x0, x1, x2,
        q00_wih, q00_whh, q00_b,
        q01_wih, q01_whh, q01_b,
        i00_wih, i00_whh, i00_b,
        i01_wih, i01_whh, i01_b,
        i02_wih, i02_whh, i02_b);

    head_kernel<<<dim3(BB / 32, 2), 256, HEAD_SMEM_BYTES>>>(
        s2,
        q03_w, q03_b, q1_w, q1_b, q2_w, q2_b,
        i03_w, i03_b, i1_w, i1_b, i2_w, i2_b,
        out);
}